// round 15
// baseline (speedup 1.0000x reference)
#include <cuda_runtime.h>
#include <math.h>
#define NB 4
#define NK 5
#define NVOX 35937
#define NJ 539055
#define CIN 320
#define CH 256
#define KTOT 2880

__device__ float g_pooled[NB*CH];
__device__ float g_lut[NB*NJ];
__device__ float g_r0[NB*NK*1024];
__device__ float g_r1[NB*NK*1024];
__device__ float g_u64a[NB*NK*4096];
__device__ float g_u64b[NB*NK*4096];
__device__ float g_u128a[NB*NK*16384];
__device__ float g_u128b[NB*NK*16384];
__device__ float g_r256[NB*NK*65536];
__device__ float g_acc[4];

// device-side scratch resolver — NEVER pass __device__ symbols from host code
__device__ __forceinline__ float* scratch(int id) {
    switch (id) {
        case 0: return g_r1;
        case 1: return g_u64a;
        case 2: return g_u64b;
        case 3: return g_u128a;
        case 4: return g_u128b;
        default: return g_r256;
    }
}

__global__ void k_init() { if (threadIdx.x < 4) g_acc[threadIdx.x] = 0.f; }

__global__ void k_pool(const float* __restrict__ feat, const float* __restrict__ W,
                       const float* __restrict__ bias) {
    __shared__ float fs[1024];
    __shared__ float ws[8][9];
    __shared__ float red[256];
    const int cog = blockIdx.x * 8, b = blockIdx.y, t = threadIdx.x;
    const float* featb = feat + (size_t)b * CIN * 1024;
    float acc[8][4];
#pragma unroll
    for (int g = 0; g < 8; g++)
#pragma unroll
        for (int i = 0; i < 4; i++) acc[g][i] = 0.f;
    const int p0 = t * 4, y = p0 >> 5, x0 = p0 & 31;
    for (int ci = 0; ci < CIN; ci++) {
        __syncthreads();
#pragma unroll
        for (int l = 0; l < 4; l++) fs[t + l*256] = featb[ci*1024 + t + l*256];
        if (t < 72) ws[t/9][t%9] = W[(size_t)(cog + t/9)*KTOT + ci*9 + (t%9)];
        __syncthreads();
#pragma unroll
        for (int i = 0; i < 4; i++) {
            int x = x0 + i;
            float tp[9];
#pragma unroll
            for (int dy = 0; dy < 3; dy++) {
                int yy = y + dy - 1;
#pragma unroll
                for (int dx = 0; dx < 3; dx++) {
                    int xx = x + dx - 1;
                    tp[dy*3+dx] = ((unsigned)yy < 32u && (unsigned)xx < 32u) ? fs[yy*32+xx] : 0.f;
                }
            }
#pragma unroll
            for (int g = 0; g < 8; g++) {
                float a = acc[g][i];
#pragma unroll
                for (int j = 0; j < 9; j++) a += ws[g][j] * tp[j];
                acc[g][i] = a;
            }
        }
    }
#pragma unroll
    for (int g = 0; g < 8; g++) {
        float bb = bias[cog + g], s = 0.f;
#pragma unroll
        for (int i = 0; i < 4; i++) s += fmaxf(acc[g][i] + bb, 0.f);
        __syncthreads();
        red[t] = s;
        __syncthreads();
        for (int off = 128; off; off >>= 1) {
            if (t < off) red[t] += red[t + off];
            __syncthreads();
        }
        if (t == 0) g_pooled[b*CH + cog + g] = red[0];
    }
}

__global__ void k_noise(const float* __restrict__ feat, const float* __restrict__ W,
                        const float* __restrict__ bias, float* __restrict__ out) {
    int b = blockIdx.y, t = threadIdx.x;
    int p = blockIdx.x*64 + (t & 63), co = t >> 6;
    int y = p >> 5, x = p & 31;
    const float* featb = feat + (size_t)b * CIN * 1024;
    const float* w = W + (size_t)co * KTOT;
    float acc = bias[co];
    for (int ci = 0; ci < CIN; ci++) {
        const float* f = featb + ci*1024;
        const float* wc = w + ci*9;
#pragma unroll
        for (int ky = 0; ky < 3; ky++) {
            int iy = y + ky - 1;
            if ((unsigned)iy < 32u)
#pragma unroll
                for (int kx = 0; kx < 3; kx++) {
                    int ix = x + kx - 1;
                    if ((unsigned)ix < 32u) acc += wc[ky*3+kx] * f[iy*32+ix];
                }
        }
    }
    out[((size_t)b*4 + co)*1024 + p] = acc;
}

__global__ void k_gemv(const float* __restrict__ W2, const float* __restrict__ b2) {
    const int lane = threadIdx.x & 31;
    const int warp0 = (blockIdx.x*blockDim.x + threadIdx.x) >> 5;
    const int nwarps = (gridDim.x*blockDim.x) >> 5;
    const float inv = 1.0f / 1024.0f;
    float pa[4][4], pb_[4][4];
#pragma unroll
    for (int b = 0; b < 4; b++)
#pragma unroll
        for (int i = 0; i < 4; i++) {
            pa[b][i]  = g_pooled[b*CH + (lane<<2) + i] * inv;
            pb_[b][i] = g_pooled[b*CH + 128 + (lane<<2) + i] * inv;
        }
    for (int j = warp0; j < NJ; j += nwarps) {
        const float4 w0 = *(const float4*)&W2[(size_t)j*256 + (lane<<2)];
        const float4 w1 = *(const float4*)&W2[(size_t)j*256 + 128 + (lane<<2)];
        float acc[4];
#pragma unroll
        for (int b = 0; b < 4; b++)
            acc[b] = w0.x*pa[b][0] + w0.y*pa[b][1] + w0.z*pa[b][2] + w0.w*pa[b][3]
                   + w1.x*pb_[b][0] + w1.y*pb_[b][1] + w1.z*pb_[b][2] + w1.w*pb_[b][3];
#pragma unroll
        for (int off = 16; off; off >>= 1)
#pragma unroll
            for (int b = 0; b < 4; b++)
                acc[b] += __shfl_xor_sync(0xffffffffu, acc[b], off);
        if (lane < 4) g_lut[(size_t)lane*NJ + j] = acc[lane] + b2[j];
    }
}

__global__ void k_r0(const float* __restrict__ feat, const float* __restrict__ w0,
                     const float* __restrict__ b0) {
    int idx = blockIdx.x*blockDim.x + threadIdx.x;
    if (idx >= NB*NK*1024) return;
    int p = idx & 1023, k = (idx >> 10) % NK, b = idx / (NK*1024);
    const float* f = feat + (size_t)b*CIN*1024 + p;
    const float* wk = w0 + k*CIN;
    float a = b0[k];
    for (int ci = 0; ci < CIN; ci++) a += wk[ci] * f[ci*1024];
    g_r0[((size_t)b*NK + k)*1024 + p] = fmaxf(a, 0.f);
}

__global__ void k_r1(const float* __restrict__ w1, const float* __restrict__ b1) {
    int idx = blockIdx.x*blockDim.x + threadIdx.x;
    if (idx >= NB*NK*1024) return;
    int p = idx & 1023, x = p & 31, y = p >> 5;
    int co = (idx >> 10) % NK, b = idx / (NK*1024);
    float a = b1[co];
#pragma unroll
    for (int ci = 0; ci < 5; ci++) {
        const float* f = g_r0 + ((size_t)b*NK + ci)*1024;
#pragma unroll
        for (int ky = 0; ky < 3; ky++) {
            int iy = y + ky - 1;
            if ((unsigned)iy >= 32u) continue;
#pragma unroll
            for (int kx = 0; kx < 3; kx++) {
                int ix = x + kx - 1;
                if ((unsigned)ix >= 32u) continue;
                a += w1[((co*5+ci)*3+ky)*3+kx] * f[iy*32+ix];
            }
        }
    }
    g_r1[((size_t)b*NK + co)*1024 + p] = fmaxf(a, 0.f);
}

__global__ void k_convt(int in_id, const float* __restrict__ w,
                        const float* __restrict__ bias, int out_id, int Hin) {
    const float* in = scratch(in_id);
    float* out = scratch(out_id);
    int Hout = Hin*2;
    int idx = blockIdx.x*blockDim.x + threadIdx.x;
    if (idx >= NB*NK*Hout*Hout) return;
    int x = idx % Hout; int t = idx / Hout;
    int y = t % Hout; t /= Hout;
    int co = t % NK, b = t / NK;
    int yhi = (y+1) >> 1, xhi = (x+1) >> 1;
    float a = bias[co];
#pragma unroll
    for (int dy = 0; dy < 2; dy++) {
        int yi = yhi - 1 + dy;
        if ((unsigned)yi >= (unsigned)Hin) continue;
        int ky = y + 1 - 2*yi;
#pragma unroll
        for (int dx = 0; dx < 2; dx++) {
            int xi = xhi - 1 + dx;
            if ((unsigned)xi >= (unsigned)Hin) continue;
            int kx = x + 1 - 2*xi;
#pragma unroll
            for (int ci = 0; ci < 5; ci++)
                a += w[((ci*5+co)*4+ky)*4+kx] * in[(((size_t)b*5+ci)*Hin+yi)*Hin+xi];
        }
    }
    out[idx] = a;
}

__global__ void k_conv5(int in_id, const float* __restrict__ w,
                        const float* __restrict__ bias, int out_id, int H) {
    const float* in = scratch(in_id);
    float* out = scratch(out_id);
    int idx = blockIdx.x*blockDim.x + threadIdx.x;
    if (idx >= NB*NK*H*H) return;
    int x = idx % H; int t = idx / H;
    int y = t % H; t /= H;
    int co = t % NK, b = t / NK;
    const float* inb = in + (size_t)(b*NK)*H*H;
    float a = bias[co];
#pragma unroll
    for (int ci = 0; ci < 5; ci++) {
        const float* f = inb + (size_t)ci*H*H;
#pragma unroll
        for (int ky = 0; ky < 3; ky++) {
            int iy = y + ky - 1;
            if ((unsigned)iy >= (unsigned)H) continue;
#pragma unroll
            for (int kx = 0; kx < 3; kx++) {
                int ix = x + kx - 1;
                if ((unsigned)ix >= (unsigned)H) continue;
                a += w[((co*5+ci)*3+ky)*3+kx] * f[iy*H+ix];
            }
        }
    }
    out[idx] = fmaxf(a, 0.f);
}

__global__ void k_fuse(const float* __restrict__ img, float* __restrict__ out) {
    int idx = blockIdx.x*blockDim.x + threadIdx.x;
    int b = idx >> 16, p = idx & 0xFFFF;
    const float* imgb = img + (size_t)b*3*65536;
    float cx = fminf(fmaxf((imgb[p]*0.5f+0.5f)*32.f, 0.f), 32.f);
    float cy = fminf(fmaxf((imgb[p+65536]*0.5f+0.5f)*32.f, 0.f), 32.f);
    float cz = fminf(fmaxf((imgb[p+131072]*0.5f+0.5f)*32.f, 0.f), 32.f);
    int x0 = min((int)cx, 31), y0 = min((int)cy, 31), z0 = min((int)cz, 31);
    float xd = cx-x0, yd = cy-y0, zd = cz-z0;
    float rv[5];
#pragma unroll
    for (int k = 0; k < 5; k++) rv[k] = g_r256[(((size_t)b*5+k)<<16) + p];
    float m = rv[0];
#pragma unroll
    for (int k = 1; k < 5; k++) m = fmaxf(m, rv[k]);
    float s = 0.f;
#pragma unroll
    for (int k = 0; k < 5; k++) { rv[k] = expf(rv[k]-m); s += rv[k]; }
    float invs = 1.f/s, pw[5], wn = 0.f;
#pragma unroll
    for (int k = 0; k < 5; k++) { pw[k] = rv[k]*invs; wn += pw[k]*pw[k]; }
    const float* lutb = g_lut + (size_t)b*NJ;
    int v000 = z0*1089 + y0*33 + x0;
    float oc[3] = {0.f, 0.f, 0.f};
#pragma unroll
    for (int k = 0; k < 5; k++)
#pragma unroll
        for (int c = 0; c < 3; c++) {
            const float* L = lutb + (size_t)(k*3+c)*NVOX + v000;
            float c00 = L[0]*(1.f-xd) + L[1]*xd;
            float c01 = L[33]*(1.f-xd) + L[34]*xd;
            float c10 = L[1089]*(1.f-xd) + L[1090]*xd;
            float c11 = L[1122]*(1.f-xd) + L[1123]*xd;
            float c0 = c00*(1.f-yd) + c01*yd;
            float c1 = c10*(1.f-yd) + c11*yd;
            oc[c] += pw[k] * (c0*(1.f-zd) + c1*zd);
        }
    size_t ob = 16384 + (size_t)b*3*65536 + p;
    out[ob] = oc[0]; out[ob+65536] = oc[1]; out[ob+131072] = oc[2];
#pragma unroll
    for (int off = 16; off; off >>= 1) wn += __shfl_xor_sync(0xffffffffu, wn, off);
    __shared__ float sh[8];
    int lane = threadIdx.x & 31, wid = threadIdx.x >> 5;
    if (lane == 0) sh[wid] = wn;
    __syncthreads();
    if (wid == 0) {
        float v = (lane < 8) ? sh[lane] : 0.f;
#pragma unroll
        for (int off = 4; off; off >>= 1) v += __shfl_xor_sync(0xffffffffu, v, off);
        if (lane == 0) atomicAdd(&g_acc[0], v);
    }
}

__global__ void k_reg() {
    int idx = blockIdx.x*blockDim.x + threadIdx.x;
    float tv = 0.f, mn = 0.f;
    if (idx < NB*NVOX) {
        int b = idx / NVOX, v = idx - b*NVOX;
        int z = v/1089, rem = v - z*1089, y = rem/33, x = rem - y*33;
        const float* Lb = g_lut + (size_t)b*NJ;
        float wrx = (x==0||x==31)?2.f:1.f, wry = (y==0||y==31)?2.f:1.f, wrz = (z==0||z==31)?2.f:1.f;
#pragma unroll
        for (int kc = 0; kc < 15; kc++) {
            const float* L = Lb + (size_t)kc*NVOX + v;
            float cur = L[0];
            if (x < 32) { float d = cur - L[1];    tv += d*d*wrx; mn += fmaxf(d, 0.f); }
            if (y < 32) { float d = cur - L[33];   tv += d*d*wry; mn += fmaxf(d, 0.f); }
            if (z < 32) { float d = cur - L[1089]; tv += d*d*wrz; mn += fmaxf(d, 0.f); }
        }
    }
#pragma unroll
    for (int off = 16; off; off >>= 1) {
        tv += __shfl_xor_sync(0xffffffffu, tv, off);
        mn += __shfl_xor_sync(0xffffffffu, mn, off);
    }
    __shared__ float sht[8], shm[8];
    int lane = threadIdx.x & 31, wid = threadIdx.x >> 5;
    if (lane == 0) { sht[wid] = tv; shm[wid] = mn; }
    __syncthreads();
    if (wid == 0) {
        float a = (lane < 8) ? sht[lane] : 0.f;
        float c = (lane < 8) ? shm[lane] : 0.f;
#pragma unroll
        for (int off = 4; off; off >>= 1) {
            a += __shfl_xor_sync(0xffffffffu, a, off);
            c += __shfl_xor_sync(0xffffffffu, c, off);
        }
        if (lane == 0) { atomicAdd(&g_acc[1], a); atomicAdd(&g_acc[2], c); }
    }
}

__global__ void k_fin(float* __restrict__ out) {
    float wn = g_acc[0] / (float)(NB*NK*65536);
    float tvc = g_acc[1] / 104544.f;
    float mnc = g_acc[2] / 104544.f;
    out[802816] = 0.0005f*(wn + tvc*0.25f) + 10.f*(mnc*0.25f);
}

extern "C" void kernel_launch(void* const* d_in, const int* in_sizes, int n_in,
                              void* d_out, int out_size) {
    const float *feat=0, *img=0, *co_w=0, *co_b=0, *lb_w1=0, *lb_b1=0, *lb_w2=0, *lb_b2=0;
    const float *rw0=0;
    const float *rw3x3[3] = {0,0,0};
    const float *rwt[3]  = {0,0,0};
    const float *rb[7]   = {0,0,0,0,0,0,0};
    int n225 = 0, n400 = 0, n5 = 0;
    for (int i = 0; i < n_in; i++) {
        const float* p = (const float*)d_in[i];
        switch (in_sizes[i]) {
            case 1310720:  feat = p; break;
            case 786432:   img = p; break;
            case 11520:    co_w = p; break;
            case 4:        co_b = p; break;
            case 737280:   lb_w1 = p; break;
            case 256:      lb_b1 = p; break;
            case 137998080: lb_w2 = p; break;
            case 539055:   lb_b2 = p; break;
            case 1600:     rw0 = p; break;
            case 225:      if (n225 < 3) rw3x3[n225++] = p; break;
            case 400:      if (n400 < 3) rwt[n400++] = p; break;
            case 5:        if (n5 < 7) rb[n5++] = p; break;
            default: break;
        }
    }
    float* out = (float*)d_out;

    k_init<<<1, 32>>>();
    k_pool<<<dim3(32, 4), 256>>>(feat, lb_w1, lb_b1);
    k_noise<<<dim3(16, 4), 256>>>(feat, co_w, co_b, out);
    k_gemv<<<2048, 256>>>(lb_w2, lb_b2);
    k_r0<<<80, 256>>>(feat, rw0, rb[0]);
    k_r1<<<80, 256>>>(rw3x3[0], rb[1]);
    int t0 = NB*NK*4096;
    k_convt<<<(t0+255)/256, 256>>>(0, rwt[0], rb[2], 1, 32);   // g_r1 -> g_u64a
    k_conv5<<<(t0+255)/256, 256>>>(1, rw3x3[1], rb[3], 2, 64); // g_u64a -> g_u64b
    int t1 = NB*NK*16384;
    k_convt<<<(t1+255)/256, 256>>>(2, rwt[1], rb[4], 3, 64);   // g_u64b -> g_u128a
    k_conv5<<<(t1+255)/256, 256>>>(3, rw3x3[2], rb[5], 4, 128);// g_u128a -> g_u128b
    int t2 = NB*NK*65536;
    k_convt<<<(t2+255)/256, 256>>>(4, rwt[2], rb[6], 5, 128);  // g_u128b -> g_r256
    k_fuse<<<1024, 256>>>(img, out);
    k_reg<<<(NB*NVOX+255)/256, 256>>>();
    k_fin<<<1, 1>>>(out);
}

// round 16
// speedup vs baseline: 1.3713x; 1.3713x over previous
#include <cuda_runtime.h>
#include <math.h>
#define NB 4
#define NK 5
#define NVOX 35937
#define NJ 539055
#define CIN 320
#define CH 256
#define KTOT 2880

__device__ __align__(16) float g_pooled[NB*CH];
__device__ __align__(16) float g_lut[NB*NVOX*16];   // [b][voxel][15 kc + pad]
__device__ float g_r0[NB*NK*1024];
__device__ float g_r1[NB*NK*1024];
__device__ float g_u64a[NB*NK*4096];
__device__ float g_u64b[NB*NK*4096];
__device__ float g_u128a[NB*NK*16384];
__device__ float g_u128b[NB*NK*16384];
__device__ float g_r256[NB*NK*65536];
__device__ float g_acc[4];

__device__ __forceinline__ float* scratch(int id) {
    switch (id) {
        case 0: return g_r1;
        case 1: return g_u64a;
        case 2: return g_u64b;
        case 3: return g_u128a;
        case 4: return g_u128b;
        default: return g_r256;
    }
}

typedef unsigned long long ull;
__device__ __forceinline__ void fma2(ull& acc, ull a, ull b) {
    asm("fma.rn.f32x2 %0, %1, %2, %0;" : "+l"(acc) : "l"(a), "l"(b));
}
__device__ __forceinline__ ull pk2(float lo, float hi) {
    ull r; asm("mov.b64 %0, {%1, %2};" : "=l"(r) : "f"(lo), "f"(hi)); return r;
}
__device__ __forceinline__ float2 upk2(ull v) {
    float2 f; asm("mov.b64 {%0, %1}, %2;" : "=f"(f.x), "=f"(f.y) : "l"(v)); return f;
}

__global__ void k_init() {
    int t = threadIdx.x;
    if (t < NB*CH) g_pooled[t] = 0.f;
    if (t < 4) g_acc[t] = 0.f;
}

// unified conv3x3 320->{256 pool | 4 noise}: halo tile + f32x2, px-split x2
// grid (33, 2, 4): x=co-group (32=noise), y=px half, z=batch. block 256, 2 px/thread.
__global__ void k_poolnoise(const float* __restrict__ feat,
                            const float* __restrict__ Wp, const float* __restrict__ bp,
                            const float* __restrict__ Wn, const float* __restrict__ bn,
                            float* __restrict__ out) {
    __shared__ float fs[34*34];
    __shared__ ull ws2[8][9];
    __shared__ float red[8];
    const int cog = blockIdx.x, ph = blockIdx.y, b = blockIdx.z, t = threadIdx.x;
    const bool noise = (cog == 32);
    const int nch = noise ? 4 : 8;
    const float* featb = feat + (size_t)b*CIN*1024;
    for (int i = t; i < 34*34; i += 256) fs[i] = 0.f;

    const int p0 = ph*512 + t*2;
    const int y = p0 >> 5, x0 = p0 & 31;     // x0 even
    ull acc2[8];
#pragma unroll
    for (int g = 0; g < 8; g++) acc2[g] = 0ull;

    for (int ci = 0; ci < CIN; ci++) {
        __syncthreads();
#pragma unroll
        for (int l = 0; l < 4; l++) {
            int pp = t + l*256;
            fs[(1 + (pp >> 5))*34 + 1 + (pp & 31)] = featb[ci*1024 + pp];
        }
        if (t < nch*9) {
            int g = t/9, jj = t - g*9;
            float w = noise ? Wn[(size_t)g*KTOT + ci*9 + jj]
                            : Wp[(size_t)(cog*8 + g)*KTOT + ci*9 + jj];
            ws2[g][jj] = pk2(w, w);
        }
        __syncthreads();
        float tp[3][4];
#pragma unroll
        for (int r = 0; r < 3; r++)
#pragma unroll
            for (int c = 0; c < 4; c++) tp[r][c] = fs[(y + r)*34 + x0 + c];
        ull p2[3][3];
#pragma unroll
        for (int r = 0; r < 3; r++)
#pragma unroll
            for (int c = 0; c < 3; c++) p2[r][c] = pk2(tp[r][c], tp[r][c+1]);
        if (noise) {
#pragma unroll
            for (int g = 0; g < 4; g++)
#pragma unroll
                for (int r = 0; r < 3; r++)
#pragma unroll
                    for (int c = 0; c < 3; c++) fma2(acc2[g], p2[r][c], ws2[g][r*3+c]);
        } else {
#pragma unroll
            for (int g = 0; g < 8; g++)
#pragma unroll
                for (int r = 0; r < 3; r++)
#pragma unroll
                    for (int c = 0; c < 3; c++) fma2(acc2[g], p2[r][c], ws2[g][r*3+c]);
        }
    }

    int lane = t & 31, wid = t >> 5;
    if (noise) {
#pragma unroll
        for (int g = 0; g < 4; g++) {
            float2 u = upk2(acc2[g]);
            float bb = bn[g];
            size_t ob = ((size_t)b*4 + g)*1024 + p0;
            out[ob] = u.x + bb; out[ob + 1] = u.y + bb;
        }
    } else {
#pragma unroll
        for (int g = 0; g < 8; g++) {
            float2 u = upk2(acc2[g]);
            float bb = bp[cog*8 + g];
            float s = fmaxf(u.x + bb, 0.f) + fmaxf(u.y + bb, 0.f);
#pragma unroll
            for (int off = 16; off; off >>= 1) s += __shfl_xor_sync(0xffffffffu, s, off);
            __syncthreads();
            if (lane == 0) red[wid] = s;
            __syncthreads();
            if (t == 0) {
                float v = 0.f;
#pragma unroll
                for (int w = 0; w < 8; w++) v += red[w];
                atomicAdd(&g_pooled[b*CH + cog*8 + g], v);
            }
        }
    }
}

// GEMV: 16 lanes per j, pooled in registers, stores padded voxel-major LUT
__global__ void k_gemv(const float* __restrict__ W2, const float* __restrict__ b2) {
    const int t = threadIdx.x;
    const int lane = t & 31, l16 = lane & 15, sub = lane >> 4;
    const float inv = 1.0f / 1024.0f;
    float4 pr[4][4];
#pragma unroll
    for (int b = 0; b < 4; b++)
#pragma unroll
        for (int i = 0; i < 4; i++) {
            float4 p = *(const float4*)&g_pooled[b*CH + l16*16 + i*4];
            pr[b][i] = make_float4(p.x*inv, p.y*inv, p.z*inv, p.w*inv);
        }
    const int gwid = (blockIdx.x*blockDim.x + t) >> 5;
    const int nw = (gridDim.x*blockDim.x) >> 5;
    for (int j = gwid*2 + sub; j < NJ; j += nw*2) {
        const float4* wr = (const float4*)(W2 + (size_t)j*256) + l16*4;
        float a0 = 0.f, a1 = 0.f, a2 = 0.f, a3 = 0.f;
#pragma unroll
        for (int i = 0; i < 4; i++) {
            float4 w = wr[i];
            a0 += w.x*pr[0][i].x + w.y*pr[0][i].y + w.z*pr[0][i].z + w.w*pr[0][i].w;
            a1 += w.x*pr[1][i].x + w.y*pr[1][i].y + w.z*pr[1][i].z + w.w*pr[1][i].w;
            a2 += w.x*pr[2][i].x + w.y*pr[2][i].y + w.z*pr[2][i].z + w.w*pr[2][i].w;
            a3 += w.x*pr[3][i].x + w.y*pr[3][i].y + w.z*pr[3][i].z + w.w*pr[3][i].w;
        }
#pragma unroll
        for (int off = 8; off; off >>= 1) {
            a0 += __shfl_down_sync(0xffffffffu, a0, off, 16);
            a1 += __shfl_down_sync(0xffffffffu, a1, off, 16);
            a2 += __shfl_down_sync(0xffffffffu, a2, off, 16);
            a3 += __shfl_down_sync(0xffffffffu, a3, off, 16);
        }
        if (l16 == 0) {
            float bb = b2[j];
            int kc = j / NVOX;
            int v = j - kc*NVOX;
            size_t base = (size_t)v*16 + kc;
            g_lut[base]                      = a0 + bb;
            g_lut[base + (size_t)NVOX*16]    = a1 + bb;
            g_lut[base + (size_t)NVOX*32]    = a2 + bb;
            g_lut[base + (size_t)NVOX*48]    = a3 + bb;
        }
    }
}

__global__ void k_r0(const float* __restrict__ feat, const float* __restrict__ w0,
                     const float* __restrict__ b0) {
    int idx = blockIdx.x*blockDim.x + threadIdx.x;
    if (idx >= NB*NK*1024) return;
    int p = idx & 1023, k = (idx >> 10) % NK, b = idx / (NK*1024);
    const float* f = feat + (size_t)b*CIN*1024 + p;
    const float* wk = w0 + k*CIN;
    float a = b0[k];
    for (int ci = 0; ci < CIN; ci++) a += wk[ci] * f[ci*1024];
    g_r0[((size_t)b*NK + k)*1024 + p] = fmaxf(a, 0.f);
}

__global__ void k_r1(const float* __restrict__ w1, const float* __restrict__ b1) {
    int idx = blockIdx.x*blockDim.x + threadIdx.x;
    if (idx >= NB*NK*1024) return;
    int p = idx & 1023, x = p & 31, y = p >> 5;
    int co = (idx >> 10) % NK, b = idx / (NK*1024);
    float a = b1[co];
#pragma unroll
    for (int ci = 0; ci < 5; ci++) {
        const float* f = g_r0 + ((size_t)b*NK + ci)*1024;
#pragma unroll
        for (int ky = 0; ky < 3; ky++) {
            int iy = y + ky - 1;
            if ((unsigned)iy >= 32u) continue;
#pragma unroll
            for (int kx = 0; kx < 3; kx++) {
                int ix = x + kx - 1;
                if ((unsigned)ix >= 32u) continue;
                a += w1[((co*5+ci)*3+ky)*3+kx] * f[iy*32+ix];
            }
        }
    }
    g_r1[((size_t)b*NK + co)*1024 + p] = fmaxf(a, 0.f);
}

__global__ void k_convt(int in_id, const float* __restrict__ w,
                        const float* __restrict__ bias, int out_id, int Hin) {
    const float* in = scratch(in_id);
    float* out = scratch(out_id);
    int Hout = Hin*2;
    int idx = blockIdx.x*blockDim.x + threadIdx.x;
    if (idx >= NB*NK*Hout*Hout) return;
    int x = idx % Hout; int t = idx / Hout;
    int y = t % Hout; t /= Hout;
    int co = t % NK, b = t / NK;
    int yhi = (y+1) >> 1, xhi = (x+1) >> 1;
    float a = bias[co];
#pragma unroll
    for (int dy = 0; dy < 2; dy++) {
        int yi = yhi - 1 + dy;
        if ((unsigned)yi >= (unsigned)Hin) continue;
        int ky = y + 1 - 2*yi;
#pragma unroll
        for (int dx = 0; dx < 2; dx++) {
            int xi = xhi - 1 + dx;
            if ((unsigned)xi >= (unsigned)Hin) continue;
            int kx = x + 1 - 2*xi;
#pragma unroll
            for (int ci = 0; ci < 5; ci++)
                a += w[((ci*5+co)*4+ky)*4+kx] * in[(((size_t)b*5+ci)*Hin+yi)*Hin+xi];
        }
    }
    out[idx] = a;
}

__global__ void k_conv5(int in_id, const float* __restrict__ w,
                        const float* __restrict__ bias, int out_id, int H) {
    const float* in = scratch(in_id);
    float* out = scratch(out_id);
    int idx = blockIdx.x*blockDim.x + threadIdx.x;
    if (idx >= NB*NK*H*H) return;
    int x = idx % H; int t = idx / H;
    int y = t % H; t /= H;
    int co = t % NK, b = t / NK;
    const float* inb = in + (size_t)(b*NK)*H*H;
    float a = bias[co];
#pragma unroll
    for (int ci = 0; ci < 5; ci++) {
        const float* f = inb + (size_t)ci*H*H;
#pragma unroll
        for (int ky = 0; ky < 3; ky++) {
            int iy = y + ky - 1;
            if ((unsigned)iy >= (unsigned)H) continue;
#pragma unroll
            for (int kx = 0; kx < 3; kx++) {
                int ix = x + kx - 1;
                if ((unsigned)ix >= (unsigned)H) continue;
                a += w[((co*5+ci)*3+ky)*3+kx] * f[iy*H+ix];
            }
        }
    }
    out[idx] = fmaxf(a, 0.f);
}

// fusion: softmax + trilerp from padded voxel-major LUT (float4 gathers) + blend
__global__ void k_fuse(const float* __restrict__ img, float* __restrict__ out) {
    int idx = blockIdx.x*blockDim.x + threadIdx.x;
    int b = idx >> 16, p = idx & 0xFFFF;
    const float* imgb = img + (size_t)b*3*65536;
    float cx = fminf(fmaxf((imgb[p]*0.5f+0.5f)*32.f, 0.f), 32.f);
    float cy = fminf(fmaxf((imgb[p+65536]*0.5f+0.5f)*32.f, 0.f), 32.f);
    float cz = fminf(fmaxf((imgb[p+131072]*0.5f+0.5f)*32.f, 0.f), 32.f);
    int x0 = min((int)cx, 31), y0 = min((int)cy, 31), z0 = min((int)cz, 31);
    float xd = cx-x0, yd = cy-y0, zd = cz-z0;
    float wx[2] = {1.f-xd, xd}, wy[2] = {1.f-yd, yd}, wz[2] = {1.f-zd, zd};

    float rv[5];
#pragma unroll
    for (int k = 0; k < 5; k++) rv[k] = g_r256[(((size_t)b*5+k)<<16) + p];
    float m = rv[0];
#pragma unroll
    for (int k = 1; k < 5; k++) m = fmaxf(m, rv[k]);
    float s = 0.f;
#pragma unroll
    for (int k = 0; k < 5; k++) { rv[k] = expf(rv[k]-m); s += rv[k]; }
    float invs = 1.f/s, pw[5], wn = 0.f;
#pragma unroll
    for (int k = 0; k < 5; k++) { pw[k] = rv[k]*invs; wn += pw[k]*pw[k]; }

    const float* lutb = g_lut + (size_t)b*NVOX*16;
    float it[16];
#pragma unroll
    for (int i = 0; i < 16; i++) it[i] = 0.f;
#pragma unroll
    for (int dz = 0; dz < 2; dz++)
#pragma unroll
    for (int dy = 0; dy < 2; dy++)
#pragma unroll
    for (int dx = 0; dx < 2; dx++) {
        float wt = wz[dz]*wy[dy]*wx[dx];
        const float4* cp = (const float4*)(lutb + (size_t)((z0+dz)*1089 + (y0+dy)*33 + (x0+dx))*16);
        float4 v0 = cp[0], v1 = cp[1], v2 = cp[2], v3 = cp[3];
        it[0]  += wt*v0.x; it[1]  += wt*v0.y; it[2]  += wt*v0.z; it[3]  += wt*v0.w;
        it[4]  += wt*v1.x; it[5]  += wt*v1.y; it[6]  += wt*v1.z; it[7]  += wt*v1.w;
        it[8]  += wt*v2.x; it[9]  += wt*v2.y; it[10] += wt*v2.z; it[11] += wt*v2.w;
        it[12] += wt*v3.x; it[13] += wt*v3.y; it[14] += wt*v3.z;
    }
    float oc0 = 0.f, oc1 = 0.f, oc2 = 0.f;
#pragma unroll
    for (int k = 0; k < 5; k++) {
        oc0 += pw[k]*it[k*3+0];
        oc1 += pw[k]*it[k*3+1];
        oc2 += pw[k]*it[k*3+2];
    }
    size_t ob = 16384 + (size_t)b*3*65536 + p;
    out[ob] = oc0; out[ob+65536] = oc1; out[ob+131072] = oc2;

#pragma unroll
    for (int off = 16; off; off >>= 1) wn += __shfl_xor_sync(0xffffffffu, wn, off);
    __shared__ float sh[8];
    int lane = threadIdx.x & 31, wid = threadIdx.x >> 5;
    if (lane == 0) sh[wid] = wn;
    __syncthreads();
    if (wid == 0) {
        float v = (lane < 8) ? sh[lane] : 0.f;
#pragma unroll
        for (int off = 4; off; off >>= 1) v += __shfl_xor_sync(0xffffffffu, v, off);
        if (lane == 0) atomicAdd(&g_acc[0], v);
    }
}

__device__ __forceinline__ void tvmn15(const float4* A, const float4* B, float wr,
                                       float& tv, float& mn) {
    float4 a0 = A[0], a1 = A[1], a2 = A[2], a3 = A[3];
    float4 b0 = B[0], b1 = B[1], b2 = B[2], b3 = B[3];
    float d;
    d = a0.x-b0.x; tv += d*d*wr; mn += fmaxf(d,0.f);
    d = a0.y-b0.y; tv += d*d*wr; mn += fmaxf(d,0.f);
    d = a0.z-b0.z; tv += d*d*wr; mn += fmaxf(d,0.f);
    d = a0.w-b0.w; tv += d*d*wr; mn += fmaxf(d,0.f);
    d = a1.x-b1.x; tv += d*d*wr; mn += fmaxf(d,0.f);
    d = a1.y-b1.y; tv += d*d*wr; mn += fmaxf(d,0.f);
    d = a1.z-b1.z; tv += d*d*wr; mn += fmaxf(d,0.f);
    d = a1.w-b1.w; tv += d*d*wr; mn += fmaxf(d,0.f);
    d = a2.x-b2.x; tv += d*d*wr; mn += fmaxf(d,0.f);
    d = a2.y-b2.y; tv += d*d*wr; mn += fmaxf(d,0.f);
    d = a2.z-b2.z; tv += d*d*wr; mn += fmaxf(d,0.f);
    d = a2.w-b2.w; tv += d*d*wr; mn += fmaxf(d,0.f);
    d = a3.x-b3.x; tv += d*d*wr; mn += fmaxf(d,0.f);
    d = a3.y-b3.y; tv += d*d*wr; mn += fmaxf(d,0.f);
    d = a3.z-b3.z; tv += d*d*wr; mn += fmaxf(d,0.f);
}

__global__ void k_reg() {
    int idx = blockIdx.x*blockDim.x + threadIdx.x;
    float tv = 0.f, mn = 0.f;
    if (idx < NB*NVOX) {
        int v = idx % NVOX;
        int z = v/1089, rem = v - z*1089, y = rem/33, x = rem - y*33;
        const float4* L = (const float4*)(g_lut + (size_t)idx*16);
        if (x < 32) tvmn15(L, L + 4,       (x==0||x==31)?2.f:1.f, tv, mn);
        if (y < 32) tvmn15(L, L + 33*4,    (y==0||y==31)?2.f:1.f, tv, mn);
        if (z < 32) tvmn15(L, L + 1089*4,  (z==0||z==31)?2.f:1.f, tv, mn);
    }
#pragma unroll
    for (int off = 16; off; off >>= 1) {
        tv += __shfl_xor_sync(0xffffffffu, tv, off);
        mn += __shfl_xor_sync(0xffffffffu, mn, off);
    }
    __shared__ float sht[8], shm[8];
    int lane = threadIdx.x & 31, wid = threadIdx.x >> 5;
    if (lane == 0) { sht[wid] = tv; shm[wid] = mn; }
    __syncthreads();
    if (wid == 0) {
        float a = (lane < 8) ? sht[lane] : 0.f;
        float c = (lane < 8) ? shm[lane] : 0.f;
#pragma unroll
        for (int off = 4; off; off >>= 1) {
            a += __shfl_xor_sync(0xffffffffu, a, off);
            c += __shfl_xor_sync(0xffffffffu, c, off);
        }
        if (lane == 0) { atomicAdd(&g_acc[1], a); atomicAdd(&g_acc[2], c); }
    }
}

__global__ void k_fin(float* __restrict__ out) {
    float wn = g_acc[0] / (float)(NB*NK*65536);
    float tvc = g_acc[1] / 104544.f;
    float mnc = g_acc[2] / 104544.f;
    out[802816] = 0.0005f*(wn + tvc*0.25f) + 10.f*(mnc*0.25f);
}

extern "C" void kernel_launch(void* const* d_in, const int* in_sizes, int n_in,
                              void* d_out, int out_size) {
    const float *feat=0, *img=0, *co_w=0, *co_b=0, *lb_w1=0, *lb_b1=0, *lb_w2=0, *lb_b2=0;
    const float *rw0=0;
    const float *rw3x3[3] = {0,0,0};
    const float *rwt[3]  = {0,0,0};
    const float *rb[7]   = {0,0,0,0,0,0,0};
    int n225 = 0, n400 = 0, n5 = 0;
    for (int i = 0; i < n_in; i++) {
        const float* p = (const float*)d_in[i];
        switch (in_sizes[i]) {
            case 1310720:  feat = p; break;
            case 786432:   img = p; break;
            case 11520:    co_w = p; break;
            case 4:        co_b = p; break;
            case 737280:   lb_w1 = p; break;
            case 256:      lb_b1 = p; break;
            case 137998080: lb_w2 = p; break;
            case 539055:   lb_b2 = p; break;
            case 1600:     rw0 = p; break;
            case 225:      if (n225 < 3) rw3x3[n225++] = p; break;
            case 400:      if (n400 < 3) rwt[n400++] = p; break;
            case 5:        if (n5 < 7) rb[n5++] = p; break;
            default: break;
        }
    }
    float* out = (float*)d_out;

    k_init<<<1, 1024>>>();
    k_poolnoise<<<dim3(33, 2, 4), 256>>>(feat, lb_w1, lb_b1, co_w, co_b, out);
    k_gemv<<<2048, 256>>>(lb_w2, lb_b2);
    k_r0<<<80, 256>>>(feat, rw0, rb[0]);
    k_r1<<<80, 256>>>(rw3x3[0], rb[1]);
    int t0 = NB*NK*4096;
    k_convt<<<(t0+255)/256, 256>>>(0, rwt[0], rb[2], 1, 32);
    k_conv5<<<(t0+255)/256, 256>>>(1, rw3x3[1], rb[3], 2, 64);
    int t1 = NB*NK*16384;
    k_convt<<<(t1+255)/256, 256>>>(2, rwt[1], rb[4], 3, 64);
    k_conv5<<<(t1+255)/256, 256>>>(3, rw3x3[2], rb[5], 4, 128);
    int t2 = NB*NK*65536;
    k_convt<<<(t2+255)/256, 256>>>(4, rwt[2], rb[6], 5, 128);
    k_fuse<<<1024, 256>>>(img, out);
    k_reg<<<(NB*NVOX+255)/256, 256>>>();
    k_fin<<<1, 1>>>(out);
}